// round 6
// baseline (speedup 1.0000x reference)
#include <cuda_runtime.h>
#include <cstdint>

#define BB 4
#define CC 512
#define HH 64
#define WWD 64
#define HWP 4096

// ---------------- device scratch (static allocation is allowed) ----------------
__device__ float g_w9[3][3][BB][9][HWP];        // [branch][dw,kse,ksr][b][tap][pix]
__device__ float g_seterm[3][BB][CC][HWP];      // se_term per branch
__device__ float g_attb[3][BB][CC][HWP];        // att (pre struc) per branch
__device__ float g_msg[3][BB][CC][HWP];         // att_new * se_term per branch
__device__ float g_chag[3][3][BB][CC];          // softmaxed channel weights

// ---------------- threefry2x32 (JAX-compatible) ----------------
__device__ __forceinline__ unsigned rotl32(unsigned v, int r) {
    return (v << r) | (v >> (32 - r));
}

__device__ __forceinline__ void threefry2x32(unsigned k0, unsigned k1,
                                             unsigned x0, unsigned x1,
                                             unsigned& o0, unsigned& o1) {
    unsigned k2 = k0 ^ k1 ^ 0x1BD11BDAu;
    x0 += k0; x1 += k1;
#define TFG(r) { x0 += x1; x1 = rotl32(x1, r); x1 ^= x0; }
    TFG(13) TFG(15) TFG(26) TFG(6)   x0 += k1; x1 += k2 + 1u;
    TFG(17) TFG(29) TFG(16) TFG(24)  x0 += k2; x1 += k0 + 2u;
    TFG(13) TFG(15) TFG(26) TFG(6)   x0 += k0; x1 += k1 + 3u;
    TFG(17) TFG(29) TFG(16) TFG(24)  x0 += k1; x1 += k2 + 4u;
    TFG(13) TFG(15) TFG(26) TFG(6)   x0 += k2; x1 += k0 + 5u;
#undef TFG
    o0 = x0; o1 = x1;
}

// XLA ErfInv32 (Giles 2012 polynomial) — matches jax lax.erf_inv on f32
__device__ __forceinline__ float erfinv_f(float x) {
    float w = -log1pf(-x * x);
    float p;
    if (w < 5.0f) {
        w -= 2.5f;
        p = 2.81022636e-08f;
        p = fmaf(p, w, 3.43273939e-07f);
        p = fmaf(p, w, -3.5233877e-06f);
        p = fmaf(p, w, -4.39150654e-06f);
        p = fmaf(p, w, 0.00021858087f);
        p = fmaf(p, w, -0.00125372503f);
        p = fmaf(p, w, -0.00417768164f);
        p = fmaf(p, w, 0.246640727f);
        p = fmaf(p, w, 1.50140941f);
    } else {
        w = sqrtf(w) - 3.0f;
        p = -0.000200214257f;
        p = fmaf(p, w, 0.000100950558f);
        p = fmaf(p, w, 0.00134934322f);
        p = fmaf(p, w, -0.00367342844f);
        p = fmaf(p, w, 0.00573950773f);
        p = fmaf(p, w, -0.0076224613f);
        p = fmaf(p, w, 0.00943887047f);
        p = fmaf(p, w, 1.00167406f);
        p = fmaf(p, w, 2.83297682f);
    }
    return p * x;
}

// ---------------- RNG + softmax: g_chag[br][i][b][c] ----------------
// grid (4 b, 3 i, 3 branch), block 512
// JAX partitionable threefry (default since 0.4.30): per-element counter
// (hi32(idx)=0, lo32(idx)=idx), 32-bit output = o0 ^ o1.
__global__ void rng_kernel() {
    int b = blockIdx.x, ii = blockIdx.y, br = blockIdx.z;
    int c = threadIdx.x;

    unsigned n = (unsigned)(br * 100 + ii);
    unsigned fk0, fk1;
    threefry2x32(0u, 42u, 0u, n, fk0, fk1);       // fold_in(key(42), n)

    unsigned flat = (unsigned)(b * CC + c);       // linear index into (4,512)
    unsigned o0, o1;
    threefry2x32(fk0, fk1, 0u, flat, o0, o1);
    unsigned bits = o0 ^ o1;

    float f = __uint_as_float((bits >> 9) | 0x3f800000u) - 1.0f;  // [0,1)
    const float lo = -0.99999994f;                                  // nextafter(-1,0)
    float u = fmaxf(lo, fmaf(f, 1.99999994f, lo));
    float val = 1.41421356237f * erfinv_f(u);

    __shared__ float red[CC];
    red[c] = val;
    __syncthreads();
    for (int s = 256; s > 0; s >>= 1) {
        if (c < s) red[c] = fmaxf(red[c], red[c + s]);
        __syncthreads();
    }
    float m = red[0];
    __syncthreads();
    float e = expf(val - m);
    red[c] = e;
    __syncthreads();
    for (int s = 256; s > 0; s >>= 1) {
        if (c < s) red[c] = red[c] + red[c + s];
        __syncthreads();
    }
    g_chag[br][ii][b][c] = e / red[0];
}

// ---------------- conv9: dw/kse/ksr (all dilated 3x3 convs) ----------------
struct ConvParams {
    const float* se;
    const float* sr;
    const float* kp[3];  const float* kpb[3];
    const float* kse[3]; const float* kseb[3];
    const float* ksr[3]; const float* ksrb[3];
};

// grid (32 y-pairs, 4 b, 3 branch), block 256 = 4 groups x 64 px
__global__ void conv9_kernel(ConvParams P) {
    int br = blockIdx.z, b = blockIdx.y;
    int y0 = blockIdx.x * 2;
    int d = (br == 0) ? 1 : ((br == 1) ? 4 : 8);
    int tid = threadIdx.x;
    int which = tid >> 6;      // 0: kp|se part, 1: kp|sr part, 2: kse|se, 3: ksr|sr
    int x = tid & 63;

    const float* src = (which == 1 || which == 3) ? P.sr : P.se;
    src += (size_t)b * CC * HWP;

    __shared__ float sw[4 * 16 * 3 * 28];   // padded weight rows (float4-friendly)

    float acc[2][9];
#pragma unroll
    for (int r = 0; r < 2; r++)
#pragma unroll
        for (int o = 0; o < 9; o++) acc[r][o] = 0.0f;

    for (int cin0 = 0; cin0 < CC; cin0 += 16) {
        __syncthreads();
        // cooperative weight load: 4 groups x 16 cin x 9 oc x 3 ky x 3 kx = 5184
        for (int e = tid; e < 4 * 16 * 81; e += 256) {
            int kx = e % 3; int t = e / 3;
            int oc = t % 9;  t /= 9;
            int ky = t % 3;  t /= 3;
            int ci = t % 16; int wq = t / 16;
            const float* base; int ocs;
            if (wq == 0)      { base = P.kp[br];            ocs = 1024 * 9; }
            else if (wq == 1) { base = P.kp[br] + 512 * 9;  ocs = 1024 * 9; }
            else if (wq == 2) { base = P.kse[br];           ocs = 512 * 9; }
            else              { base = P.ksr[br];           ocs = 512 * 9; }
            sw[((wq * 16 + ci) * 3 + ky) * 28 + oc * 3 + kx] =
                __ldg(base + (size_t)oc * ocs + (size_t)(cin0 + ci) * 9 + ky * 3 + kx);
        }
        __syncthreads();

        for (int ci = 0; ci < 16; ci++) {
            const float* chan = src + (size_t)(cin0 + ci) * HWP;
#pragma unroll
            for (int ky = 0; ky < 3; ky++) {
                const float4* wp4 = (const float4*)&sw[((which * 16 + ci) * 3 + ky) * 28];
                float wv[28] __attribute__((aligned(16)));
#pragma unroll
                for (int q = 0; q < 7; q++) ((float4*)wv)[q] = wp4[q];
#pragma unroll
                for (int ry = 0; ry < 2; ry++) {
                    int yy = y0 + ry + (ky - 1) * d;
                    if ((unsigned)yy < 64u) {
                        const float* row = chan + yy * WWD;
                        float vm = (x - d >= 0) ? __ldg(row + x - d) : 0.0f;
                        float v0 = __ldg(row + x);
                        float vp = (x + d < 64) ? __ldg(row + x + d) : 0.0f;
#pragma unroll
                        for (int oc = 0; oc < 9; oc++) {
                            float a = acc[ry][oc];
                            a = fmaf(wv[oc * 3 + 0], vm, a);
                            a = fmaf(wv[oc * 3 + 1], v0, a);
                            a = fmaf(wv[oc * 3 + 2], vp, a);
                            acc[ry][oc] = a;
                        }
                    }
                }
            }
        }
    }

    __syncthreads();
    float* sacc = sw;   // reuse: need 4*9*2*64 = 4608 <= 5376
#pragma unroll
    for (int ry = 0; ry < 2; ry++)
#pragma unroll
        for (int oc = 0; oc < 9; oc++)
            sacc[((which * 9 + oc) * 2 + ry) * 64 + x] = acc[ry][oc];
    __syncthreads();

    // combine: dw = grp0+grp1+kpb ; kse = grp2+kseb ; ksr = grp3+ksrb
    for (int e = tid; e < 27 * 2 * 64; e += 256) {
        int xx = e & 63; int t = e >> 6;
        int ry = t % 2; int oc = (t / 2) % 9; int ow = t / 18;
        float v;
        if (ow == 0)
            v = sacc[((0 * 9 + oc) * 2 + ry) * 64 + xx] +
                sacc[((1 * 9 + oc) * 2 + ry) * 64 + xx] + __ldg(P.kpb[br] + oc);
        else if (ow == 1)
            v = sacc[((2 * 9 + oc) * 2 + ry) * 64 + xx] + __ldg(P.kseb[br] + oc);
        else
            v = sacc[((3 * 9 + oc) * 2 + ry) * 64 + xx] + __ldg(P.ksrb[br] + oc);
        g_w9[br][ow][b][oc][(y0 + ry) * 64 + xx] = v;
    }
}

// ---------------- att assembly: se_term + att ----------------
// grid (64 y, 4 b, 3 branch), block 256 = 64 px x 4 c-parallel
__global__ void att_kernel(const float* __restrict__ se, const float* __restrict__ sr) {
    int br = blockIdx.z, b = blockIdx.y, y = blockIdx.x;
    int d = (br == 0) ? 1 : ((br == 1) ? 4 : 8);
    int tid = threadIdx.x;
    int x = tid & 63, cp = tid >> 6;
    int p = y * 64 + x;

    float wdw[9], wkse[9], wksr[9];
#pragma unroll
    for (int k = 0; k < 9; k++) {
        wdw[k]  = g_w9[br][0][b][k][p];
        wkse[k] = g_w9[br][1][b][k][p];
        wksr[k] = g_w9[br][2][b][k][p];
    }
    const float* seb = se + (size_t)b * CC * HWP;
    const float* srb = sr + (size_t)b * CC * HWP;

    for (int c = cp; c < CC; c += 4) {
        const float* sep = seb + (size_t)c * HWP;
        const float* srp = srb + (size_t)c * HWP;
        float st = 0.0f, t2 = 0.0f, t3 = 0.0f, ctr_sr = 0.0f;
#pragma unroll
        for (int ky = 0; ky < 3; ky++) {
            int yy = y + (ky - 1) * d;
            bool yok = (unsigned)yy < 64u;
#pragma unroll
            for (int kx = 0; kx < 3; kx++) {
                int xx = x + (kx - 1) * d;
                bool ok = yok && ((unsigned)xx < 64u);
                int off = yy * WWD + xx;
                float vs = ok ? __ldg(sep + off) : 0.0f;
                float vr = ok ? __ldg(srp + off) : 0.0f;
                int k = ky * 3 + kx;
                st = fmaf(wdw[k], vs, st);
                t2 = fmaf(wkse[k], vs, t2);
                t3 = fmaf(wksr[k], vr, t3);
                if (k == 4) ctr_sr = vr;
            }
        }
        float a = fmaf(ctr_sr, st, t2 + t3);
        g_seterm[br][b][c][p] = st;
        g_attb[br][b][c][p] = a;
    }
}

// ---------------- fused spatial gate + struc_att + msg (and att1 output) ----------------
// grid (64 y, 4 b, 3 branch), block 256 = 64 px x 4 c-parallel
// Pass 1: reduce sum_c chag[i][c]*att[c][p] -> sigmoid -> sp[i] (in smem)
// Pass 2: gate att, write g_msg and att1.
__global__ void gate_kernel(float* __restrict__ out, long long out_elems,
                            const int* __restrict__ rankp) {
    int br = blockIdx.z, b = blockIdx.y, y = blockIdx.x;
    int tid = threadIdx.x;
    int x = tid & 63, cp = tid >> 6;
    int p = y * 64 + x;

    int rk = 3;
    if (rankp) {
        int v = *rankp;
        if (v >= 0 && v < 16) rk = v;
        else {
            float f = __int_as_float(v);
            int fi = (int)f;
            if (fi >= 0 && fi < 16) rk = fi;
        }
    }
    if (rk > 3) rk = 3;

    __shared__ float sch[3][CC];
    for (int e = tid; e < 3 * CC; e += 256)
        sch[e >> 9][e & 511] = g_chag[br][e >> 9][b][e & 511];
    __syncthreads();

    // ---- pass 1: channel reduction for the 3 spatial gates ----
    float a0 = 0.0f, a1 = 0.0f, a2 = 0.0f;
    for (int c = cp; c < CC; c += 4) {
        float a = g_attb[br][b][c][p];
        a0 = fmaf(sch[0][c], a, a0);
        a1 = fmaf(sch[1][c], a, a1);
        a2 = fmaf(sch[2][c], a, a2);
    }
    __shared__ float sred[4][3][64];
    sred[cp][0][x] = a0; sred[cp][1][x] = a1; sred[cp][2][x] = a2;
    __syncthreads();
    __shared__ float ssp[3][64];
    if (cp == 0) {
#pragma unroll
        for (int i = 0; i < 3; i++) {
            float s = sred[0][i][x] + sred[1][i][x] + sred[2][i][x] + sred[3][i][x];
            ssp[i][x] = 1.0f / (1.0f + expf(-s));
        }
    }
    __syncthreads();

    float sp0 = ssp[0][x];
    float sp1 = ssp[1][x];
    float sp2 = ssp[2][x];

    bool write_att1 = (br == 0) && (out_elems >= 2LL * BB * CC * HWP);

    // ---- pass 2: apply gating, produce msg (+ att1) ----
    for (int c = cp; c < CC; c += 4) {
        float a = g_attb[br][b][c][p];
        float s;
        if (rk == 0) s = 1.0f;
        else {
            s = sp0 * sch[0][c];
            if (rk > 1) s = fmaf(sp1, sch[1][c], s);
            if (rk > 2) s = fmaf(sp2, sch[2][c], s);
        }
        float an = a * s;
        g_msg[br][b][c][p] = an * g_seterm[br][b][c][p];
        if (write_att1)
            out[(size_t)BB * CC * HWP + ((size_t)(b * CC + c)) * HWP + p] = an;
    }
}

// ---------------- final 1x1 conv: SGEMM 512 x 16384 x 1536 + bias + relu ----------------
// grid (128 n-tiles, 4 m-tiles), block 256, tile 128x128x16, 8x8 per thread
__global__ void gemm_kernel(const float* __restrict__ Wc,
                            const float* __restrict__ bias,
                            float* __restrict__ out) {
    __shared__ float As[16][128];
    __shared__ float Bs[16][128];

    int tid = threadIdx.x;
    int nt = blockIdx.x, mt = blockIdx.y;
    int n0 = nt * 128;
    int bidx = n0 >> 12;        // batch
    int p0 = n0 & 4095;

    int arow = tid >> 1;             // 0..127 (output channel within tile)
    int acol = (tid & 1) * 8;        // 0 or 8
    const float* Aptr = Wc + (size_t)(mt * 128 + arow) * 1536 + acol;

    int brow = tid >> 5;             // 0..7
    int bcol = (tid & 31) * 4;       // 0..124

    int tx = tid & 15, ty = tid >> 4;
    int m0 = ty * 8, n0t = tx * 8;

    const float* msgf = &g_msg[0][0][0][0];

    float acc[8][8];
#pragma unroll
    for (int i = 0; i < 8; i++)
#pragma unroll
        for (int j = 0; j < 8; j++) acc[i][j] = 0.0f;

    for (int k0 = 0; k0 < 1536; k0 += 16) {
        float4 a0 = *(const float4*)(Aptr + k0);
        float4 a1 = *(const float4*)(Aptr + k0 + 4);
        As[acol + 0][arow] = a0.x; As[acol + 1][arow] = a0.y;
        As[acol + 2][arow] = a0.z; As[acol + 3][arow] = a0.w;
        As[acol + 4][arow] = a1.x; As[acol + 5][arow] = a1.y;
        As[acol + 6][arow] = a1.z; As[acol + 7][arow] = a1.w;
#pragma unroll
        for (int rr = 0; rr < 2; rr++) {
            int r = brow + rr * 8;
            int i = k0 + r;                      // global K index
            const float* bp = msgf +
                (((size_t)(i >> 9) * BB + bidx) * CC + (i & 511)) * HWP + p0 + bcol;
            *(float4*)&Bs[r][bcol] = *(const float4*)bp;
        }
        __syncthreads();

#pragma unroll
        for (int kk = 0; kk < 16; kk++) {
            float a[8], bv[8];
            *(float4*)&a[0]  = *(float4*)&As[kk][m0];
            *(float4*)&a[4]  = *(float4*)&As[kk][m0 + 4];
            *(float4*)&bv[0] = *(float4*)&Bs[kk][n0t];
            *(float4*)&bv[4] = *(float4*)&Bs[kk][n0t + 4];
#pragma unroll
            for (int i = 0; i < 8; i++)
#pragma unroll
                for (int j = 0; j < 8; j++)
                    acc[i][j] = fmaf(a[i], bv[j], acc[i][j]);
        }
        __syncthreads();
    }

#pragma unroll
    for (int i = 0; i < 8; i++) {
        int o = mt * 128 + m0 + i;
        float bi = __ldg(bias + o);
        float* orow = out + (size_t)bidx * CC * HWP + (size_t)o * HWP + p0 + n0t;
#pragma unroll
        for (int j = 0; j < 8; j += 4) {
            float4 r;
            r.x = fmaxf(acc[i][j + 0] + bi, 0.0f);
            r.y = fmaxf(acc[i][j + 1] + bi, 0.0f);
            r.z = fmaxf(acc[i][j + 2] + bi, 0.0f);
            r.w = fmaxf(acc[i][j + 3] + bi, 0.0f);
            *(float4*)(orow + j) = r;
        }
    }
}

// ---------------- launch ----------------
extern "C" void kernel_launch(void* const* d_in, const int* in_sizes, int n_in,
                              void* d_out, int out_size) {
    const float* sr = (const float*)d_in[0];
    const float* se = (const float*)d_in[1];

    ConvParams P;
    P.se = se; P.sr = sr;
    P.kp[0]  = (const float*)d_in[2];  P.kpb[0]  = (const float*)d_in[3];
    P.kp[1]  = (const float*)d_in[4];  P.kpb[1]  = (const float*)d_in[5];
    P.kp[2]  = (const float*)d_in[6];  P.kpb[2]  = (const float*)d_in[7];
    P.kse[0] = (const float*)d_in[8];  P.kseb[0] = (const float*)d_in[9];
    P.ksr[0] = (const float*)d_in[10]; P.ksrb[0] = (const float*)d_in[11];
    P.kse[1] = (const float*)d_in[12]; P.kseb[1] = (const float*)d_in[13];
    P.ksr[1] = (const float*)d_in[14]; P.ksrb[1] = (const float*)d_in[15];
    P.kse[2] = (const float*)d_in[16]; P.kseb[2] = (const float*)d_in[17];
    P.ksr[2] = (const float*)d_in[18]; P.ksrb[2] = (const float*)d_in[19];
    const float* comb_w = (const float*)d_in[20];
    const float* comb_b = (const float*)d_in[21];
    const int* rankp = (n_in >= 24) ? (const int*)d_in[23] : nullptr;

    rng_kernel<<<dim3(4, 3, 3), 512>>>();
    conv9_kernel<<<dim3(32, 4, 3), 256>>>(P);
    att_kernel<<<dim3(64, 4, 3), 256>>>(se, sr);
    gate_kernel<<<dim3(64, 4, 3), 256>>>((float*)d_out, (long long)out_size, rankp);
    gemm_kernel<<<dim3(128, 4), 256>>>(comb_w, comb_b, (float*)d_out);
}